// round 16
// baseline (speedup 1.0000x reference)
#include <cuda_runtime.h>
#include <cuda_bf16.h>
#include <cuda_fp16.h>
#include <cuda_fp8.h>
#include <cstdint>
#include <cstddef>

#define B_ROWS 4096
#define D_DIM  1024
#define N2     8192
#define INV_T  2.0f
#define NT     64                  // 128-wide tiles per dimension
#define TT     (NT*(NT+1)/2)       // 2080 upper-triangular tiles
#define PTILE_OFF 32               // bx == by + 32 tiles hold the positive pairs

// Scratch (device globals; no allocation allowed)
__device__ uint8_t g_reps8[(size_t)N2 * D_DIM];  // normalized reps, e4m3
__device__ float   g_rowsum[N2];                 // sum_{c != r} exp(sim[r][c]/T)
__device__ float   g_possum;                     // sum over r<B of sim(r, r+B)/T
__device__ unsigned int g_done;                  // simexp completion counter

// ---------------------------------------------------------------------------
// Kernel 1: L2-normalize rows -> e4m3 reps; warp-per-row (MLP=8, no smem)
// ---------------------------------------------------------------------------
__global__ void normalize_kernel(const float* __restrict__ emb_i,
                                 const float* __restrict__ emb_j,
                                 float* __restrict__ out)
{
    int t = threadIdx.x;
    int wid = t >> 5, lane = t & 31;
    int row = blockIdx.x * 8 + wid;              // 1024 blocks x 8 warps
    const float* src = (row < B_ROWS) ? (emb_i + (size_t)row * D_DIM)
                                      : (emb_j + (size_t)(row - B_ROWS) * D_DIM);

    float4 v[8];
    #pragma unroll
    for (int i = 0; i < 8; i++) v[i] = ((const float4*)src)[i * 32 + lane];

    float ss = 0.0f;
    #pragma unroll
    for (int i = 0; i < 8; i++)
        ss += v[i].x * v[i].x + v[i].y * v[i].y + v[i].z * v[i].z + v[i].w * v[i].w;
    #pragma unroll
    for (int o = 16; o; o >>= 1) ss += __shfl_xor_sync(0xFFFFFFFFu, ss, o);

    float rinv = 1.0f / fmaxf(sqrtf(ss), 1e-12f);

    uint32_t* dst = (uint32_t*)(g_reps8 + (size_t)row * D_DIM);
    #pragma unroll
    for (int i = 0; i < 8; i++) {
        __nv_fp8x2_e4m3 p0(make_float2(v[i].x * rinv, v[i].y * rinv));
        __nv_fp8x2_e4m3 p1(make_float2(v[i].z * rinv, v[i].w * rinv));
        dst[i * 32 + lane] = (uint32_t)*(uint16_t*)&p0 | ((uint32_t)*(uint16_t*)&p1 << 16);
    }

    if (blockIdx.x < 32) g_rowsum[blockIdx.x * 256 + t] = 0.0f;
    if (blockIdx.x == 0 && t == 0) { out[0] = 0.0f; g_possum = 0.0f; g_done = 0u; }
}

// ---------------------------------------------------------------------------
// Kernel 2: fused exp(2 * Z Z^T) row-sum, upper-triangular tiles.
// FP8 e4m3 QMMA, f16 accumulators, 128x128 CTA tile, 2-stage cp.async.
// R11 structure with BK=128 (8 stages, HALF the barriers). Dynamic smem.
// ---------------------------------------------------------------------------
#define BK    128                 // fp8 elems (=bytes) per k-stage
#define NKT   (D_DIM / BK)        // 8 k-stages
#define SSTR  144                 // padded smem row stride in BYTES (128 + 16)
#define SM_MAT   (128 * SSTR)     // 18432 bytes per matrix per stage
#define SM_A(st) ((st) * 2 * SM_MAT)
#define SM_B(st) ((st) * 2 * SM_MAT + SM_MAT)
#define SMEM_DYN (4 * SM_MAT)     // 73728 bytes

__global__ __launch_bounds__(256, 2)
void simexp_kernel(float* __restrict__ out)
{
    extern __shared__ uint8_t dsm[];

    // decode linear tile index -> (by, bx) with bx >= by
    int idx = blockIdx.x;
    int by = (int)((2.0f * NT + 1.0f
              - sqrtf((float)((2 * NT + 1) * (2 * NT + 1) - 8 * idx))) * 0.5f);
    while ((by * (2 * NT - by + 1)) / 2 > idx) by--;
    while (((by + 1) * (2 * NT - by)) / 2 <= idx) by++;
    int bx = by + idx - (by * (2 * NT - by + 1)) / 2;
    bool offdiag = (bx != by);
    bool postile = (bx == by + PTILE_OFF);

    int tid  = threadIdx.x;
    int wid  = tid >> 5, lane = tid & 31;
    int warp_m = wid & 1;     // 0..1  -> 64-row slab
    int warp_n = wid >> 1;    // 0..3  -> 32-col slab

    bool skip_warp = !offdiag && (warp_m == 1) && (warp_n < 2);
    bool do_col    = offdiag || ((warp_m == 0) && (warp_n >= 2));

    const uint8_t* Abase = g_reps8 + (size_t)(by * 128) * D_DIM;
    const uint8_t* Bbase = g_reps8 + (size_t)(bx * 128) * D_DIM;

    // cooperative cp.async: 128 rows x 128B per matrix = 1024 16B-chunks,
    // 4 per thread per matrix: row = tid>>1, cols (tid&1)*64 + i*16
    int l_r  = tid >> 1;
    int l_cb = (tid & 1) * 64;

    #define LOAD_STAGE(kt, st)                                                        \
    {                                                                                 \
        _Pragma("unroll")                                                             \
        for (int i = 0; i < 4; i++) {                                                 \
            int off = l_cb + i * 16;                                                  \
            const uint8_t* ga = Abase + (size_t)l_r * D_DIM + (kt) + off;             \
            uint32_t da = (uint32_t)__cvta_generic_to_shared(                         \
                              dsm + SM_A(st) + l_r * SSTR + off);                     \
            asm volatile("cp.async.cg.shared.global [%0], [%1], 16;" ::               \
                         "r"(da), "l"(ga));                                           \
            const uint8_t* gb = Bbase + (size_t)l_r * D_DIM + (kt) + off;             \
            uint32_t db = (uint32_t)__cvta_generic_to_shared(                         \
                              dsm + SM_B(st) + l_r * SSTR + off);                     \
            asm volatile("cp.async.cg.shared.global [%0], [%1], 16;" ::               \
                         "r"(db), "l"(gb));                                           \
        }                                                                             \
        asm volatile("cp.async.commit_group;");                                       \
    }

    uint32_t facc[4][4][2];
    #pragma unroll
    for (int mi = 0; mi < 4; mi++)
        #pragma unroll
        for (int ni = 0; ni < 4; ni++)
            { facc[mi][ni][0] = 0u; facc[mi][ni][1] = 0u; }

    LOAD_STAGE(0, 0);

    for (int kt = 0; kt < NKT; kt++) {
        int st = kt & 1;
        if (kt + 1 < NKT) {
            LOAD_STAGE((kt + 1) * BK, (kt + 1) & 1);
            asm volatile("cp.async.wait_group 1;");
        } else {
            asm volatile("cp.async.wait_group 0;");
        }
        __syncthreads();

        if (!skip_warp) {
            #pragma unroll
            for (int ks = 0; ks < 4; ks++) {
                int kb = ks * 32;                        // byte offset of k32 chunk
                uint32_t a[4][4];
                #pragma unroll
                for (int mi = 0; mi < 4; mi++) {
                    int row = warp_m * 64 + mi * 16 + (lane & 15);
                    int col = kb + ((lane >> 4) << 4);
                    uint32_t addr = (uint32_t)__cvta_generic_to_shared(
                                        dsm + SM_A(st) + row * SSTR + col);
                    asm volatile("ldmatrix.sync.aligned.m8n8.x4.shared.b16 {%0,%1,%2,%3}, [%4];"
                                 : "=r"(a[mi][0]), "=r"(a[mi][1]), "=r"(a[mi][2]), "=r"(a[mi][3])
                                 : "r"(addr));
                }
                uint32_t b[4][2];
                #pragma unroll
                for (int ni = 0; ni < 4; ni++) {
                    int row = warp_n * 32 + ni * 8 + (lane & 7);
                    int col = kb + (((lane >> 3) & 1) << 4);
                    uint32_t addr = (uint32_t)__cvta_generic_to_shared(
                                        dsm + SM_B(st) + row * SSTR + col);
                    asm volatile("ldmatrix.sync.aligned.m8n8.x2.shared.b16 {%0,%1}, [%2];"
                                 : "=r"(b[ni][0]), "=r"(b[ni][1])
                                 : "r"(addr));
                }
                #pragma unroll
                for (int mi = 0; mi < 4; mi++)
                    #pragma unroll
                    for (int ni = 0; ni < 4; ni++)
                        asm volatile(
                            "mma.sync.aligned.m16n8k32.row.col.f16.e4m3.e4m3.f16 "
                            "{%0,%1}, {%2,%3,%4,%5}, {%6,%7}, {%0,%1};"
                            : "+r"(facc[mi][ni][0]), "+r"(facc[mi][ni][1])
                            : "r"(a[mi][0]), "r"(a[mi][1]), "r"(a[mi][2]), "r"(a[mi][3]),
                              "r"(b[ni][0]), "r"(b[ni][1]));
            }
        }
        __syncthreads();
    }

    // ---------------- Epilogue ----------------
    int grow_base = by * 128 + warp_m * 64;
    int gcol_base = bx * 128 + warp_n * 32;
    int lr = lane >> 2;
    int lc = (lane & 3) * 2;

    if (!skip_warp) {
        float colacc[4][2];
        #pragma unroll
        for (int ni = 0; ni < 4; ni++) { colacc[ni][0] = 0.0f; colacc[ni][1] = 0.0f; }

        #pragma unroll
        for (int mi = 0; mi < 4; mi++) {
            int r0 = grow_base + mi * 16 + lr;
            int r1 = r0 + 8;
            float s0 = 0.0f, s1 = 0.0f;
            #pragma unroll
            for (int ni = 0; ni < 4; ni++) {
                int c0 = gcol_base + ni * 8 + lc;
                float2 v01 = __half22float2(*(const __half2*)&facc[mi][ni][0]);
                float2 v23 = __half22float2(*(const __half2*)&facc[mi][ni][1]);
                float e00 = (r0 != c0)     ? __expf(v01.x * INV_T) : 0.0f;
                float e01 = (r0 != c0 + 1) ? __expf(v01.y * INV_T) : 0.0f;
                float e10 = (r1 != c0)     ? __expf(v23.x * INV_T) : 0.0f;
                float e11 = (r1 != c0 + 1) ? __expf(v23.y * INV_T) : 0.0f;
                s0 += e00 + e01;
                s1 += e10 + e11;
                colacc[ni][0] += e00 + e10;
                colacc[ni][1] += e01 + e11;
            }
            s0 += __shfl_xor_sync(0xFFFFFFFFu, s0, 1);
            s0 += __shfl_xor_sync(0xFFFFFFFFu, s0, 2);
            s1 += __shfl_xor_sync(0xFFFFFFFFu, s1, 1);
            s1 += __shfl_xor_sync(0xFFFFFFFFu, s1, 2);
            if ((lane & 3) == 0) {
                atomicAdd(&g_rowsum[r0], s0);
                atomicAdd(&g_rowsum[r1], s1);
            }
        }

        if (do_col) {
            #pragma unroll
            for (int ni = 0; ni < 4; ni++) {
                float c0 = colacc[ni][0], c1 = colacc[ni][1];
                #pragma unroll
                for (int o = 4; o <= 16; o <<= 1) {
                    c0 += __shfl_xor_sync(0xFFFFFFFFu, c0, o);
                    c1 += __shfl_xor_sync(0xFFFFFFFFu, c1, o);
                }
                if (lane < 4) {
                    int c = gcol_base + ni * 8 + lane * 2;
                    atomicAdd(&g_rowsum[c],     c0);
                    atomicAdd(&g_rowsum[c + 1], c1);
                }
            }
        }

        if (postile) {
            float pacc = 0.0f;
            #pragma unroll
            for (int mi = 0; mi < 4; mi++) {
                int r0 = grow_base + mi * 16 + lr;
                int r1 = r0 + 8;
                #pragma unroll
                for (int ni = 0; ni < 4; ni++) {
                    int c0 = gcol_base + ni * 8 + lc;
                    float2 v01 = __half22float2(*(const __half2*)&facc[mi][ni][0]);
                    float2 v23 = __half22float2(*(const __half2*)&facc[mi][ni][1]);
                    if (c0 == r0 + B_ROWS)     pacc += v01.x * INV_T;
                    if (c0 + 1 == r0 + B_ROWS) pacc += v01.y * INV_T;
                    if (c0 == r1 + B_ROWS)     pacc += v23.x * INV_T;
                    if (c0 + 1 == r1 + B_ROWS) pacc += v23.y * INV_T;
                }
            }
            #pragma unroll
            for (int o = 16; o; o >>= 1) pacc += __shfl_xor_sync(0xFFFFFFFFu, pacc, o);
            if (lane == 0 && pacc != 0.0f) atomicAdd(&g_possum, pacc);
        }
    }

    // ---------------- Fused finalize: last CTA computes the loss ----------
    __syncthreads();
    __threadfence();
    __shared__ unsigned int s_last;
    __shared__ float s_red[8];
    if (tid == 0) s_last = (atomicAdd(&g_done, 1u) == TT - 1) ? 1u : 0u;
    __syncthreads();
    if (s_last) {
        __threadfence();
        float lsum = 0.0f;
        for (int r = tid; r < N2; r += 256) lsum += logf(g_rowsum[r]);
        #pragma unroll
        for (int o = 16; o; o >>= 1) lsum += __shfl_xor_sync(0xFFFFFFFFu, lsum, o);
        if (lane == 0) s_red[wid] = lsum;
        __syncthreads();
        if (tid < 32) {
            float s = (tid < 8) ? s_red[tid] : 0.0f;
            #pragma unroll
            for (int o = 4; o; o >>= 1) s += __shfl_xor_sync(0xFFFFFFFFu, s, o);
            if (tid == 0)
                out[0] = (s - 2.0f * g_possum) * (1.0f / (float)N2);
        }
    }
}

// ---------------------------------------------------------------------------
extern "C" void kernel_launch(void* const* d_in, const int* in_sizes, int n_in,
                              void* d_out, int out_size)
{
    const float* emb_i = (const float*)d_in[0];
    const float* emb_j = (const float*)d_in[1];
    float* out = (float*)d_out;

    cudaFuncSetAttribute(simexp_kernel,
                         cudaFuncAttributeMaxDynamicSharedMemorySize, SMEM_DYN);

    normalize_kernel<<<1024, 256>>>(emb_i, emb_j, out);
    simexp_kernel<<<TT, 256, SMEM_DYN>>>(out);
}

// round 17
// speedup vs baseline: 1.1993x; 1.1993x over previous
#include <cuda_runtime.h>
#include <cuda_bf16.h>
#include <cuda_fp16.h>
#include <cuda_fp8.h>
#include <cstdint>
#include <cstddef>

#define B_ROWS 4096
#define D_DIM  1024
#define N2     8192
#define INV_T  2.0f
#define NT     64                  // 128-wide tiles per dimension
#define TT     (NT*(NT+1)/2)       // 2080 upper-triangular tiles
#define PTILE_OFF 32               // bx == by + 32 tiles hold the positive pairs

// Scratch (device globals; no allocation allowed)
__device__ uint8_t g_reps8[(size_t)N2 * D_DIM];  // normalized reps, e4m3
__device__ float   g_rowsum[N2];                 // sum_{c != r} exp(sim[r][c]/T)
__device__ float   g_possum;                     // sum over r<B of sim(r, r+B)/T
__device__ unsigned int g_done;                  // simexp completion counter

// ---------------------------------------------------------------------------
// Kernel 1: L2-normalize rows -> e4m3 reps; warp-per-row (MLP=8, no smem)
// ---------------------------------------------------------------------------
__global__ void normalize_kernel(const float* __restrict__ emb_i,
                                 const float* __restrict__ emb_j,
                                 float* __restrict__ out)
{
    int t = threadIdx.x;
    int wid = t >> 5, lane = t & 31;
    int row = blockIdx.x * 8 + wid;              // 1024 blocks x 8 warps
    const float* src = (row < B_ROWS) ? (emb_i + (size_t)row * D_DIM)
                                      : (emb_j + (size_t)(row - B_ROWS) * D_DIM);

    float4 v[8];
    #pragma unroll
    for (int i = 0; i < 8; i++) v[i] = ((const float4*)src)[i * 32 + lane];

    float ss = 0.0f;
    #pragma unroll
    for (int i = 0; i < 8; i++)
        ss += v[i].x * v[i].x + v[i].y * v[i].y + v[i].z * v[i].z + v[i].w * v[i].w;
    #pragma unroll
    for (int o = 16; o; o >>= 1) ss += __shfl_xor_sync(0xFFFFFFFFu, ss, o);

    float rinv = 1.0f / fmaxf(sqrtf(ss), 1e-12f);

    uint32_t* dst = (uint32_t*)(g_reps8 + (size_t)row * D_DIM);
    #pragma unroll
    for (int i = 0; i < 8; i++) {
        __nv_fp8x2_e4m3 p0(make_float2(v[i].x * rinv, v[i].y * rinv));
        __nv_fp8x2_e4m3 p1(make_float2(v[i].z * rinv, v[i].w * rinv));
        dst[i * 32 + lane] = (uint32_t)*(uint16_t*)&p0 | ((uint32_t)*(uint16_t*)&p1 << 16);
    }

    if (blockIdx.x < 32) g_rowsum[blockIdx.x * 256 + t] = 0.0f;
    if (blockIdx.x == 0 && t == 0) { out[0] = 0.0f; g_possum = 0.0f; g_done = 0u; }
}

// ---------------------------------------------------------------------------
// Kernel 2: fused exp(2 * Z Z^T) row-sum, upper-triangular tiles.
// FP8 e4m3 QMMA, f16 accumulators, 128x128 CTA tile, BK=64, 2-stage cp.async.
// Diagonal tiles skip the redundant lower-left quadrant (symmetry).
// Last CTA computes the final loss (fused finalize).
// ---------------------------------------------------------------------------
#define BK    64
#define NKT   (D_DIM / BK)        // 16 k-stages
#define SSTR  80                  // padded smem row stride in BYTES (64 + 16)

__global__ __launch_bounds__(256, 2)
void simexp_kernel(float* __restrict__ out)
{
    __shared__ uint8_t sA[2][128 * SSTR];
    __shared__ uint8_t sB[2][128 * SSTR];

    // decode linear tile index -> (by, bx) with bx >= by
    int idx = blockIdx.x;
    int by = (int)((2.0f * NT + 1.0f
              - sqrtf((float)((2 * NT + 1) * (2 * NT + 1) - 8 * idx))) * 0.5f);
    while ((by * (2 * NT - by + 1)) / 2 > idx) by--;
    while (((by + 1) * (2 * NT - by)) / 2 <= idx) by++;
    int bx = by + idx - (by * (2 * NT - by + 1)) / 2;
    bool offdiag = (bx != by);
    bool postile = (bx == by + PTILE_OFF);

    int tid  = threadIdx.x;
    int wid  = tid >> 5, lane = tid & 31;
    int warp_m = wid & 1;     // 0..1  -> 64-row slab
    int warp_n = wid >> 1;    // 0..3  -> 32-col slab

    bool skip_warp = !offdiag && (warp_m == 1) && (warp_n < 2);
    bool do_col    = offdiag || ((warp_m == 0) && (warp_n >= 2));

    // ---- hoisted cp.async addressing (per thread); pointers advance by BK ----
    int l_r  = tid >> 2;
    int l_c4 = tid & 3;
    const uint8_t* gA0 = g_reps8 + ((size_t)(by * 128) + l_r) * D_DIM + l_c4 * 16;
    const uint8_t* gA1 = gA0 + (size_t)64 * D_DIM;
    const uint8_t* gB0 = g_reps8 + ((size_t)(bx * 128) + l_r) * D_DIM + l_c4 * 16;
    const uint8_t* gB1 = gB0 + (size_t)64 * D_DIM;
    uint32_t dOffA  = (uint32_t)(l_r * SSTR + l_c4 * 16);
    uint32_t dOffA1 = dOffA + 64 * SSTR;

    uint32_t saddrA[2], saddrB[2];
    saddrA[0] = (uint32_t)__cvta_generic_to_shared(&sA[0][0]);
    saddrA[1] = (uint32_t)__cvta_generic_to_shared(&sA[1][0]);
    saddrB[0] = (uint32_t)__cvta_generic_to_shared(&sB[0][0]);
    saddrB[1] = (uint32_t)__cvta_generic_to_shared(&sB[1][0]);

    #define LOAD_STAGE(st)                                                         \
    {                                                                              \
        asm volatile("cp.async.cg.shared.global [%0], [%1], 16;" ::                \
                     "r"(saddrA[st] + dOffA), "l"(gA0));                           \
        asm volatile("cp.async.cg.shared.global [%0], [%1], 16;" ::                \
                     "r"(saddrA[st] + dOffA1), "l"(gA1));                          \
        asm volatile("cp.async.cg.shared.global [%0], [%1], 16;" ::                \
                     "r"(saddrB[st] + dOffA), "l"(gB0));                           \
        asm volatile("cp.async.cg.shared.global [%0], [%1], 16;" ::                \
                     "r"(saddrB[st] + dOffA1), "l"(gB1));                          \
        asm volatile("cp.async.commit_group;");                                    \
        gA0 += BK; gA1 += BK; gB0 += BK; gB1 += BK;                                \
    }

    // ---- hoisted ldmatrix offsets (bytes within a stage buffer) ----
    uint32_t aoff[4], boff[4];
    #pragma unroll
    for (int mi = 0; mi < 4; mi++)
        aoff[mi] = (uint32_t)((warp_m * 64 + mi * 16 + (lane & 15)) * SSTR
                              + ((lane >> 4) << 4));
    #pragma unroll
    for (int ni = 0; ni < 4; ni++)
        boff[ni] = (uint32_t)((warp_n * 32 + ni * 8 + (lane & 7)) * SSTR
                              + (((lane >> 3) & 1) << 4));

    uint32_t facc[4][4][2];
    #pragma unroll
    for (int mi = 0; mi < 4; mi++)
        #pragma unroll
        for (int ni = 0; ni < 4; ni++)
            { facc[mi][ni][0] = 0u; facc[mi][ni][1] = 0u; }

    LOAD_STAGE(0);

    for (int kt = 0; kt < NKT; kt++) {
        int st = kt & 1;
        if (kt + 1 < NKT) {
            LOAD_STAGE((kt + 1) & 1);
            asm volatile("cp.async.wait_group 1;");
        } else {
            asm volatile("cp.async.wait_group 0;");
        }
        __syncthreads();

        if (!skip_warp) {
            uint32_t sa = saddrA[st];
            uint32_t sb = saddrB[st];
            #pragma unroll
            for (int ks = 0; ks < 2; ks++) {
                uint32_t kb = ks * 32;
                uint32_t a[4][4];
                #pragma unroll
                for (int mi = 0; mi < 4; mi++)
                    asm volatile("ldmatrix.sync.aligned.m8n8.x4.shared.b16 {%0,%1,%2,%3}, [%4];"
                                 : "=r"(a[mi][0]), "=r"(a[mi][1]), "=r"(a[mi][2]), "=r"(a[mi][3])
                                 : "r"(sa + aoff[mi] + kb));
                uint32_t b[4][2];
                #pragma unroll
                for (int ni = 0; ni < 4; ni++)
                    asm volatile("ldmatrix.sync.aligned.m8n8.x2.shared.b16 {%0,%1}, [%2];"
                                 : "=r"(b[ni][0]), "=r"(b[ni][1])
                                 : "r"(sb + boff[ni] + kb));
                #pragma unroll
                for (int mi = 0; mi < 4; mi++)
                    #pragma unroll
                    for (int ni = 0; ni < 4; ni++)
                        asm volatile(
                            "mma.sync.aligned.m16n8k32.row.col.f16.e4m3.e4m3.f16 "
                            "{%0,%1}, {%2,%3,%4,%5}, {%6,%7}, {%0,%1};"
                            : "+r"(facc[mi][ni][0]), "+r"(facc[mi][ni][1])
                            : "r"(a[mi][0]), "r"(a[mi][1]), "r"(a[mi][2]), "r"(a[mi][3]),
                              "r"(b[ni][0]), "r"(b[ni][1]));
            }
        }
        __syncthreads();
    }

    // ---------------- Epilogue ----------------
    int grow_base = by * 128 + warp_m * 64;
    int gcol_base = bx * 128 + warp_n * 32;
    int lr = lane >> 2;
    int lc = (lane & 3) * 2;

    if (!skip_warp) {
        float colacc[4][2];
        #pragma unroll
        for (int ni = 0; ni < 4; ni++) { colacc[ni][0] = 0.0f; colacc[ni][1] = 0.0f; }

        #pragma unroll
        for (int mi = 0; mi < 4; mi++) {
            int r0 = grow_base + mi * 16 + lr;
            int r1 = r0 + 8;
            float s0 = 0.0f, s1 = 0.0f;
            #pragma unroll
            for (int ni = 0; ni < 4; ni++) {
                int c0 = gcol_base + ni * 8 + lc;
                float2 v01 = __half22float2(*(const __half2*)&facc[mi][ni][0]);
                float2 v23 = __half22float2(*(const __half2*)&facc[mi][ni][1]);
                float e00 = (r0 != c0)     ? __expf(v01.x * INV_T) : 0.0f;
                float e01 = (r0 != c0 + 1) ? __expf(v01.y * INV_T) : 0.0f;
                float e10 = (r1 != c0)     ? __expf(v23.x * INV_T) : 0.0f;
                float e11 = (r1 != c0 + 1) ? __expf(v23.y * INV_T) : 0.0f;
                s0 += e00 + e01;
                s1 += e10 + e11;
                colacc[ni][0] += e00 + e10;
                colacc[ni][1] += e01 + e11;
            }
            s0 += __shfl_xor_sync(0xFFFFFFFFu, s0, 1);
            s0 += __shfl_xor_sync(0xFFFFFFFFu, s0, 2);
            s1 += __shfl_xor_sync(0xFFFFFFFFu, s1, 1);
            s1 += __shfl_xor_sync(0xFFFFFFFFu, s1, 2);
            if ((lane & 3) == 0) {
                atomicAdd(&g_rowsum[r0], s0);
                atomicAdd(&g_rowsum[r1], s1);
            }
        }

        if (do_col) {
            #pragma unroll
            for (int ni = 0; ni < 4; ni++) {
                float c0 = colacc[ni][0], c1 = colacc[ni][1];
                #pragma unroll
                for (int o = 4; o <= 16; o <<= 1) {
                    c0 += __shfl_xor_sync(0xFFFFFFFFu, c0, o);
                    c1 += __shfl_xor_sync(0xFFFFFFFFu, c1, o);
                }
                if (lane < 4) {
                    int c = gcol_base + ni * 8 + lane * 2;
                    atomicAdd(&g_rowsum[c],     c0);
                    atomicAdd(&g_rowsum[c + 1], c1);
                }
            }
        }

        if (postile) {
            float pacc = 0.0f;
            #pragma unroll
            for (int mi = 0; mi < 4; mi++) {
                int r0 = grow_base + mi * 16 + lr;
                int r1 = r0 + 8;
                #pragma unroll
                for (int ni = 0; ni < 4; ni++) {
                    int c0 = gcol_base + ni * 8 + lc;
                    float2 v01 = __half22float2(*(const __half2*)&facc[mi][ni][0]);
                    float2 v23 = __half22float2(*(const __half2*)&facc[mi][ni][1]);
                    if (c0 == r0 + B_ROWS)     pacc += v01.x * INV_T;
                    if (c0 + 1 == r0 + B_ROWS) pacc += v01.y * INV_T;
                    if (c0 == r1 + B_ROWS)     pacc += v23.x * INV_T;
                    if (c0 + 1 == r1 + B_ROWS) pacc += v23.y * INV_T;
                }
            }
            #pragma unroll
            for (int o = 16; o; o >>= 1) pacc += __shfl_xor_sync(0xFFFFFFFFu, pacc, o);
            if (lane == 0 && pacc != 0.0f) atomicAdd(&g_possum, pacc);
        }
    }

    // ---------------- Fused finalize: last CTA computes the loss ----------
    __syncthreads();
    __threadfence();
    __shared__ unsigned int s_last;
    __shared__ float s_red[8];
    if (tid == 0) s_last = (atomicAdd(&g_done, 1u) == TT - 1) ? 1u : 0u;
    __syncthreads();
    if (s_last) {
        __threadfence();
        float lsum = 0.0f;
        for (int r = tid; r < N2; r += 256) lsum += logf(g_rowsum[r]);
        #pragma unroll
        for (int o = 16; o; o >>= 1) lsum += __shfl_xor_sync(0xFFFFFFFFu, lsum, o);
        if (lane == 0) s_red[wid] = lsum;
        __syncthreads();
        if (tid < 32) {
            float s = (tid < 8) ? s_red[tid] : 0.0f;
            #pragma unroll
            for (int o = 4; o; o >>= 1) s += __shfl_xor_sync(0xFFFFFFFFu, s, o);
            if (tid == 0)
                out[0] = (s - 2.0f * g_possum) * (1.0f / (float)N2);
        }
    }
}

// ---------------------------------------------------------------------------
extern "C" void kernel_launch(void* const* d_in, const int* in_sizes, int n_in,
                              void* d_out, int out_size)
{
    const float* emb_i = (const float*)d_in[0];
    const float* emb_j = (const float*)d_in[1];
    float* out = (float*)d_out;

    normalize_kernel<<<1024, 256>>>(emb_i, emb_j, out);
    simexp_kernel<<<TT, 256>>>(out);
}